// round 6
// baseline (speedup 1.0000x reference)
#include <cuda_runtime.h>
#include <cuda_bf16.h>

// loss = -(1/B) * sum_b [ 1 / (sum_j sigmoid(x[b,j] - x[b,0]) + 0.5) ]
// B = 32, N = 2048. Only row i=0 of the reference's [B,N,N] pair matrix is
// ever used, so compute the O(B*N) reduction directly.
//
// Single-launch version: per-batch blocks write partials to __device__
// scratch; the last-arriving block (wrapping atomicInc, so state returns to 0
// after every call -> graph-replay deterministic) reduces the 32 partials and
// writes the scalar output. No init kernel, no atomics on d_out.

#define RB 32  // batch count (grid size)

static __device__ float        g_partial[RB];
static __device__ unsigned int g_count = 0;

static __global__ void __launch_bounds__(256) rankloss_fused_kernel(
    const float* __restrict__ x, float* __restrict__ out, int N, float inv_B)
{
    const int b   = blockIdx.x;
    const int tid = threadIdx.x;
    const float* row = x + (size_t)b * N;

    const float x0 = __ldg(row);

    // Each thread reduces N/(256*4) = 2 float4 chunks (N=2048).
    const float4* row4 = reinterpret_cast<const float4*>(row);
    const int n4 = N >> 2;  // 512

    float s = 0.0f;
    #pragma unroll 4
    for (int i = tid; i < n4; i += 256) {
        float4 v = __ldg(row4 + i);
        // sigmoid(v - x0) = 1 / (1 + exp(x0 - v))
        s += __fdividef(1.0f, 1.0f + __expf(x0 - v.x));
        s += __fdividef(1.0f, 1.0f + __expf(x0 - v.y));
        s += __fdividef(1.0f, 1.0f + __expf(x0 - v.z));
        s += __fdividef(1.0f, 1.0f + __expf(x0 - v.w));
    }

    // warp reduce
    #pragma unroll
    for (int o = 16; o > 0; o >>= 1)
        s += __shfl_xor_sync(0xFFFFFFFFu, s, o);

    __shared__ float warp_sums[8];
    __shared__ int   is_last;
    const int warp = tid >> 5;
    const int lane = tid & 31;
    if (lane == 0) warp_sums[warp] = s;
    __syncthreads();

    if (tid == 0) {
        float t = warp_sums[0];
        #pragma unroll
        for (int w = 1; w < 8; w++) t += warp_sums[w];
        float rr = 1.0f / (t + 0.5f);
        g_partial[b] = -rr * inv_B;
        __threadfence();
        // wraps: returns old value; resets to 0 when old == RB-1, so the
        // counter is back at 0 after every kernel_launch (replay-safe).
        unsigned int prev = atomicInc(&g_count, RB - 1);
        is_last = (prev == RB - 1) ? 1 : 0;
    }
    __syncthreads();

    // Last-arriving block: warp 0 reduces the RB partials and writes out.
    if (is_last && warp == 0) {
        __threadfence();  // acquire: order partial reads after counter obs
        float p = g_partial[lane];  // RB == warp size
        #pragma unroll
        for (int o = 16; o > 0; o >>= 1)
            p += __shfl_xor_sync(0xFFFFFFFFu, p, o);
        if (lane == 0) out[0] = p;
    }
}

extern "C" void kernel_launch(void* const* d_in, const int* in_sizes, int n_in,
                              void* d_out, int out_size) {
    const float* x = (const float*)d_in[0];
    float* out = (float*)d_out;

    const int total = in_sizes[0];   // B * N = 65536
    const int N = 2048;
    const int B = total / N;         // 32 == RB

    rankloss_fused_kernel<<<B, 256>>>(x, out, N, 1.0f / (float)B);
}

// round 7
// speedup vs baseline: 1.1991x; 1.1991x over previous
#include <cuda_runtime.h>
#include <cuda_bf16.h>

// loss = -(1/B) * sum_b [ 1 / (sum_j sigmoid(x[b,j] - x[b,0]) + 0.5) ]
// B = 32, N = 2048. Only row i=0 of the reference's [B,N,N] pair matrix is
// used, so compute the O(B*N) reduction directly.
//
// Single-launch, cheap-tail version:
//  - each of the 32 blocks reduces one row, stores its partial (plain STG),
//  - publishes with ONE atom.global.acq_rel.gpu.inc.u32 (wrap at B-1, so the
//    counter is back to 0 after every launch -> graph-replay deterministic;
//    acq_rel replaces the two expensive __threadfence() calls, whose
//    gpu-scope fence implies an L1D flush on sm_103a),
//  - the last-arriving block's warp 0 reads the 32 partials via ld.global.cg
//    (L2-direct) and writes the scalar output. No init kernel.

#define RB 32  // batch count (grid size)

static __device__ float        g_partial[RB];
static __device__ unsigned int g_count = 0;

static __global__ void __launch_bounds__(256) rankloss_fused_kernel(
    const float* __restrict__ x, float* __restrict__ out, int N, float inv_B)
{
    const int b   = blockIdx.x;
    const int tid = threadIdx.x;
    const float* row = x + (size_t)b * N;

    const float x0 = __ldg(row);

    // N = 2048 -> 512 float4; 256 threads -> exactly 2 loads per thread.
    // Front-batch both loads (MLP=2) so the DRAM latencies overlap.
    const float4* row4 = reinterpret_cast<const float4*>(row);
    float4 v0 = __ldg(row4 + tid);
    float4 v1 = __ldg(row4 + tid + 256);

    // sigmoid(v - x0) = 1 / (1 + exp(x0 - v))
    float s = 0.0f;
    s += __fdividef(1.0f, 1.0f + __expf(x0 - v0.x));
    s += __fdividef(1.0f, 1.0f + __expf(x0 - v0.y));
    s += __fdividef(1.0f, 1.0f + __expf(x0 - v0.z));
    s += __fdividef(1.0f, 1.0f + __expf(x0 - v0.w));
    s += __fdividef(1.0f, 1.0f + __expf(x0 - v1.x));
    s += __fdividef(1.0f, 1.0f + __expf(x0 - v1.y));
    s += __fdividef(1.0f, 1.0f + __expf(x0 - v1.z));
    s += __fdividef(1.0f, 1.0f + __expf(x0 - v1.w));

    // warp reduce
    #pragma unroll
    for (int o = 16; o > 0; o >>= 1)
        s += __shfl_xor_sync(0xFFFFFFFFu, s, o);

    __shared__ float warp_sums[8];
    const int warp = tid >> 5;
    const int lane = tid & 31;
    if (lane == 0) warp_sums[warp] = s;
    __syncthreads();

    if (warp == 0) {
        float t = (lane < 8) ? warp_sums[lane] : 0.0f;
        t += __shfl_xor_sync(0xFFFFFFFFu, t, 4);
        t += __shfl_xor_sync(0xFFFFFFFFu, t, 2);
        t += __shfl_xor_sync(0xFFFFFFFFu, t, 1);

        unsigned int prev = 0u;
        if (lane == 0) {
            float rr = 1.0f / (t + 0.5f);
            g_partial[b] = -rr * inv_B;           // plain STG -> L2
            // Release my partial + wrap-increment the arrival counter.
            // atomicInc semantics: old>=31 ? 0 : old+1 (returns old), so the
            // counter returns to 0 after all 32 blocks arrive.
            asm volatile(
                "atom.global.acq_rel.gpu.inc.u32 %0, [%1], %2;"
                : "=r"(prev)
                : "l"(&g_count), "r"(RB - 1u)
                : "memory");
        }
        prev = __shfl_sync(0xFFFFFFFFu, prev, 0);

        if (prev == RB - 1u) {
            // Last arriver: acq_rel RMW synchronized with all other blocks'
            // release-incs -> their partial stores are visible. Read L2-direct.
            float p;
            asm volatile("ld.global.cg.f32 %0, [%1];"
                         : "=f"(p) : "l"(g_partial + lane) : "memory");
            #pragma unroll
            for (int o = 16; o > 0; o >>= 1)
                p += __shfl_xor_sync(0xFFFFFFFFu, p, o);
            if (lane == 0) out[0] = p;
        }
    }
}

extern "C" void kernel_launch(void* const* d_in, const int* in_sizes, int n_in,
                              void* d_out, int out_size) {
    const float* x = (const float*)d_in[0];
    float* out = (float*)d_out;

    const int total = in_sizes[0];   // B * N = 65536
    const int N = 2048;
    const int B = total / N;         // 32 == RB

    rankloss_fused_kernel<<<B, 256>>>(x, out, N, 1.0f / (float)B);
}

// round 8
// speedup vs baseline: 1.2452x; 1.0385x over previous
#include <cuda_runtime.h>
#include <cuda_bf16.h>

// loss = -(1/B) * sum_b [ 1 / (sum_j sigmoid(x[b,j] - x[b,0]) + 0.5) ]
// B = 32, N = 2048. Only row i=0 of the reference's [B,N,N] pair matrix is
// used, so compute the O(B*N) reduction directly.
//
// Single-launch, minimal-tail version:
//  - each of 32 blocks reduces one row,
//  - lane 0 fire-and-forget red.release.add's its partial into ONE __device__
//    accumulator (REDG, no return value -> no stall),
//  - one atom.acq_rel.gpu.inc wrap-counter (back to 0 after 32 arrivals ->
//    graph-replay deterministic) detects the last block,
//  - the winner does a single ld.acquire of the fully-accumulated sum, writes
//    the scalar output, and resets the accumulator for the next replay.

#define RB 32  // batch count (grid size)

static __device__ float        g_acc   = 0.0f;
static __device__ unsigned int g_count = 0;

static __global__ void __launch_bounds__(256) rankloss_fused_kernel(
    const float* __restrict__ x, float* __restrict__ out, int N, float inv_B)
{
    const int b   = blockIdx.x;
    const int tid = threadIdx.x;
    const float* row = x + (size_t)b * N;

    const float x0 = __ldg(row);

    // N = 2048 -> 512 float4; 256 threads -> exactly 2 loads per thread.
    // Front-batch both loads (MLP=2) so the DRAM latencies overlap.
    const float4* row4 = reinterpret_cast<const float4*>(row);
    float4 v0 = __ldg(row4 + tid);
    float4 v1 = __ldg(row4 + tid + 256);

    // sigmoid(v - x0) = 1 / (1 + exp(x0 - v))
    float s = 0.0f;
    s += __fdividef(1.0f, 1.0f + __expf(x0 - v0.x));
    s += __fdividef(1.0f, 1.0f + __expf(x0 - v0.y));
    s += __fdividef(1.0f, 1.0f + __expf(x0 - v0.z));
    s += __fdividef(1.0f, 1.0f + __expf(x0 - v0.w));
    s += __fdividef(1.0f, 1.0f + __expf(x0 - v1.x));
    s += __fdividef(1.0f, 1.0f + __expf(x0 - v1.y));
    s += __fdividef(1.0f, 1.0f + __expf(x0 - v1.z));
    s += __fdividef(1.0f, 1.0f + __expf(x0 - v1.w));

    // warp reduce
    #pragma unroll
    for (int o = 16; o > 0; o >>= 1)
        s += __shfl_xor_sync(0xFFFFFFFFu, s, o);

    __shared__ float warp_sums[8];
    const int warp = tid >> 5;
    const int lane = tid & 31;
    if (lane == 0) warp_sums[warp] = s;
    __syncthreads();

    if (tid == 0) {
        // 7-FADD chain (28 cyc) beats a shfl tree (~78 cyc) here.
        float t = warp_sums[0] + warp_sums[1] + warp_sums[2] + warp_sums[3]
                + warp_sums[4] + warp_sums[5] + warp_sums[6] + warp_sums[7];
        float part = -(1.0f / (t + 0.5f)) * inv_B;

        // Fire-and-forget accumulate with release semantics.
        asm volatile("red.release.gpu.global.add.f32 [%0], %1;"
                     :: "l"(&g_acc), "f"(part) : "memory");

        // Wrap-increment arrival counter: returns old; old==31 -> resets to 0,
        // so the counter is 0 again after every launch (replay-safe). acq_rel
        // pairs with all blocks' release-reds: when prev==31, g_acc is final.
        unsigned int prev;
        asm volatile("atom.acq_rel.gpu.global.inc.u32 %0, [%1], %2;"
                     : "=r"(prev) : "l"(&g_count), "r"((unsigned)(RB - 1))
                     : "memory");

        if (prev == RB - 1u) {
            float total;
            asm volatile("ld.acquire.gpu.global.f32 %0, [%1];"
                         : "=f"(total) : "l"(&g_acc) : "memory");
            out[0] = total;
            // Reset accumulator for the next graph replay. All 32 blocks have
            // arrived (counter proof), so no red.add can race with this.
            asm volatile("st.relaxed.gpu.global.f32 [%0], %1;"
                         :: "l"(&g_acc), "f"(0.0f) : "memory");
        }
    }
}

extern "C" void kernel_launch(void* const* d_in, const int* in_sizes, int n_in,
                              void* d_out, int out_size) {
    const float* x = (const float*)d_in[0];
    float* out = (float*)d_out;

    const int total = in_sizes[0];   // B * N = 65536
    const int N = 2048;
    const int B = total / N;         // 32 == RB

    rankloss_fused_kernel<<<B, 256>>>(x, out, N, 1.0f / (float)B);
}